// round 8
// baseline (speedup 1.0000x reference)
#include <cuda_runtime.h>
#include <cuda_bf16.h>
#include <math.h>
#include <stdint.h>

#define BATCH 2
#define SEQ   2048
#define EMB   1024
#define NH    16
#define HD    64

// Scratch: Q,K,V,attended in [B,H,S,D] layout. 4 x 16MB device globals.
__device__ float g_Q[BATCH*NH*SEQ*HD];
__device__ float g_K[BATCH*NH*SEQ*HD];
__device__ float g_V[BATCH*NH*SEQ*HD];
__device__ float g_att[BATCH*NH*SEQ*HD];

// ===========================================================================
// helpers
// ===========================================================================
__device__ __forceinline__ uint32_t smem_u32(const void* p) {
    uint32_t a;
    asm("{ .reg .u64 t; cvta.to.shared.u64 t, %1; cvt.u32.u64 %0, t; }"
        : "=r"(a) : "l"(p));
    return a;
}
__device__ __forceinline__ uint32_t lds_u32(uint32_t a) {
    uint32_t v;
    asm volatile("ld.shared.b32 %0, [%1];" : "=r"(v) : "r"(a));
    return v;
}
__device__ __forceinline__ void sts_v2(uint32_t a, uint32_t x, uint32_t y) {
    asm volatile("st.shared.v2.b32 [%0], {%1, %2};" :: "r"(a), "r"(x), "r"(y) : "memory");
}

// bf16 MMA m16n8k16, fp32 accumulate (portable path, sm_80+)
__device__ __forceinline__ void mma16816(float* c, const uint32_t* a, const uint32_t* b) {
    asm volatile(
        "mma.sync.aligned.m16n8k16.row.col.f32.bf16.bf16.f32 "
        "{%0,%1,%2,%3}, {%4,%5,%6,%7}, {%8,%9}, {%0,%1,%2,%3};"
        : "+f"(c[0]), "+f"(c[1]), "+f"(c[2]), "+f"(c[3])
        : "r"(a[0]), "r"(a[1]), "r"(a[2]), "r"(a[3]), "r"(b[0]), "r"(b[1]));
}

// packed f32x2 ops (base sm_100 feature, not 'a'-gated)
__device__ __forceinline__ unsigned long long pk2(float lo, float hi) {
    unsigned long long r;
    asm("mov.b64 %0, {%1, %2};" : "=l"(r) : "f"(lo), "f"(hi));
    return r;
}
__device__ __forceinline__ void upk2(float& lo, float& hi, unsigned long long v) {
    asm("mov.b64 {%0, %1}, %2;" : "=f"(lo), "=f"(hi) : "l"(v));
}
__device__ __forceinline__ void fma2(unsigned long long& d, unsigned long long a,
                                     unsigned long long b) {
    asm("fma.rn.f32x2 %0, %1, %2, %0;" : "+l"(d) : "l"(a), "l"(b));
}
__device__ __forceinline__ void mul2(unsigned long long& d, unsigned long long a) {
    asm("mul.rn.f32x2 %0, %0, %1;" : "+l"(d) : "l"(a));
}

__device__ __forceinline__ uint32_t pkbf(__nv_bfloat16 a, __nv_bfloat16 b) {
    return ((uint32_t)__bfloat16_as_ushort(b) << 16) | __bfloat16_as_ushort(a);
}

// split float4 into bf16 hi plane (x,y) and lo plane (z,w)
__device__ __forceinline__ uint4 split4(float4 v) {
    __nv_bfloat16 h0 = __float2bfloat16(v.x);
    __nv_bfloat16 h1 = __float2bfloat16(v.y);
    __nv_bfloat16 h2 = __float2bfloat16(v.z);
    __nv_bfloat16 h3 = __float2bfloat16(v.w);
    __nv_bfloat16 l0 = __float2bfloat16(v.x - __bfloat162float(h0));
    __nv_bfloat16 l1 = __float2bfloat16(v.y - __bfloat162float(h1));
    __nv_bfloat16 l2 = __float2bfloat16(v.z - __bfloat162float(h2));
    __nv_bfloat16 l3 = __float2bfloat16(v.w - __bfloat162float(h3));
    uint4 u;
    u.x = pkbf(h0, h1); u.y = pkbf(h2, h3);
    u.z = pkbf(l0, l1); u.w = pkbf(l2, l3);
    return u;
}

// ===========================================================================
// MMA projection GEMM: C[4096][1024] = A(4096x1024) * W(1024x1024)^T + bias
// fp32 via bf16 3-plane split. CTA tile 128x128, 8 warps (2Mx4N), warp tile
// 64x32, BK=32, double-buffered smem. Pitch 40 bf16 (80B) -> conflict-free
// fragment LDS (8 row-groups land on 8 disjoint 4-bank sets).
// MODE 0: A linear, C remapped to [B,H,S,D].  MODE 1: A remapped, C linear.
// ===========================================================================
#define BK      32
#define PITCHB  80                  // bytes per smem row (40 bf16)
#define PLANE   (128*PITCHB)        // 10240 B
#define BUFSZ   (4*PLANE)           // Ahi,Alo,Whi,Wlo = 40960 B
#define PJ_SMEM (2*BUFSZ)           // 81920 B

template<int MODE>
__global__ void __launch_bounds__(256, 1)
proj_mma(const float* __restrict__ A, const float* __restrict__ W,
         const float* __restrict__ bias, float* __restrict__ C)
{
    extern __shared__ char smp[];
    const uint32_t sb = smem_u32(smp);
    const int tid  = threadIdx.x;
    const int wid  = tid >> 5, lane = tid & 31;
    const int g    = lane >> 2, tg = lane & 3;
    const int wM   = wid >> 2;          // 0..1
    const int wN   = wid & 3;           // 0..3
    const int n0   = blockIdx.x * 128;
    const int m0   = blockIdx.y * 128;

    float acc[4][4][4];
    #pragma unroll
    for (int mt = 0; mt < 4; mt++)
        #pragma unroll
        for (int nt = 0; nt < 4; nt++)
            #pragma unroll
            for (int i = 0; i < 4; i++) acc[mt][nt][i] = 0.f;

    float4 avA[4], avW[4];

    // ---- global load of one K chunk into registers ----
    auto gload = [&](int kb) {
        const int k0 = kb * BK;
        #pragma unroll
        for (int i = 0; i < 4; i++) {
            const int idx = i * 256 + tid;
            const int r = idx >> 3, c4 = (idx & 7) << 2;
            if (MODE == 0) {
                avA[i] = *(const float4*)(A + (size_t)(m0 + r) * EMB + k0 + c4);
            } else {
                const int m = m0 + r;
                const int b = m >> 11, s = m & 2047;
                const int k = k0 + c4;
                const int h = k >> 6, d = k & 63;
                avA[i] = *(const float4*)(A + ((size_t)((b*NH + h)*SEQ + s))*HD + d);
            }
            avW[i] = *(const float4*)(W + (size_t)(n0 + r) * EMB + k0 + c4);
        }
    };

    // ---- convert+store the staged chunk into smem buffer ----
    auto cvtstore = [&](int buf) {
        const uint32_t base = sb + (uint32_t)buf * BUFSZ;
        #pragma unroll
        for (int i = 0; i < 4; i++) {
            const int idx = i * 256 + tid;
            const int r = idx >> 3, c4 = (idx & 7) << 2;
            const uint32_t off = (uint32_t)(r * PITCHB + c4 * 2);
            uint4 ua = split4(avA[i]);
            sts_v2(base + off,              ua.x, ua.y);     // A hi
            sts_v2(base + PLANE + off,      ua.z, ua.w);     // A lo
            uint4 uw = split4(avW[i]);
            sts_v2(base + 2*PLANE + off,    uw.x, uw.y);     // W hi
            sts_v2(base + 3*PLANE + off,    uw.z, uw.w);     // W lo
        }
    };

    // ---- MMA over one chunk ----
    auto mma_chunk = [&](int buf) {
        const uint32_t aH = sb + (uint32_t)buf * BUFSZ;
        const uint32_t aL = aH + PLANE;
        const uint32_t bH = aH + 2*PLANE;
        const uint32_t bL = aH + 3*PLANE;
        #pragma unroll
        for (int ks = 0; ks < 2; ks++) {
            const uint32_t kOff = (uint32_t)(ks * 32);   // 16 bf16 = 32 B
            uint32_t Ah[4][4], Al[4][4], Bh[4][2], Bl[4][2];
            #pragma unroll
            for (int mt = 0; mt < 4; mt++) {
                const uint32_t ro = (uint32_t)((wM*64 + mt*16 + g) * PITCHB) + kOff + tg*4;
                Ah[mt][0] = lds_u32(aH + ro);
                Ah[mt][1] = lds_u32(aH + ro + 8*PITCHB);
                Ah[mt][2] = lds_u32(aH + ro + 16);
                Ah[mt][3] = lds_u32(aH + ro + 8*PITCHB + 16);
                Al[mt][0] = lds_u32(aL + ro);
                Al[mt][1] = lds_u32(aL + ro + 8*PITCHB);
                Al[mt][2] = lds_u32(aL + ro + 16);
                Al[mt][3] = lds_u32(aL + ro + 8*PITCHB + 16);
            }
            #pragma unroll
            for (int nt = 0; nt < 4; nt++) {
                const uint32_t ro = (uint32_t)((wN*32 + nt*8 + g) * PITCHB) + kOff + tg*4;
                Bh[nt][0] = lds_u32(bH + ro);
                Bh[nt][1] = lds_u32(bH + ro + 16);
                Bl[nt][0] = lds_u32(bL + ro);
                Bl[nt][1] = lds_u32(bL + ro + 16);
            }
            #pragma unroll
            for (int mt = 0; mt < 4; mt++)
                #pragma unroll
                for (int nt = 0; nt < 4; nt++)
                    mma16816(acc[mt][nt], Ah[mt], Bh[nt]);
            #pragma unroll
            for (int mt = 0; mt < 4; mt++)
                #pragma unroll
                for (int nt = 0; nt < 4; nt++)
                    mma16816(acc[mt][nt], Al[mt], Bh[nt]);
            #pragma unroll
            for (int mt = 0; mt < 4; mt++)
                #pragma unroll
                for (int nt = 0; nt < 4; nt++)
                    mma16816(acc[mt][nt], Ah[mt], Bl[nt]);
        }
    };

    gload(0);
    cvtstore(0);
    __syncthreads();

    for (int kb = 0; kb < EMB/BK; kb++) {
        const int cur = kb & 1;
        if (kb < EMB/BK - 1) gload(kb + 1);
        mma_chunk(cur);
        if (kb < EMB/BK - 1) {
            cvtstore(cur ^ 1);
            __syncthreads();
        }
    }

    // ---- epilogue: bias + store (with layout remap) ----
    #pragma unroll
    for (int mt = 0; mt < 4; mt++) {
        #pragma unroll
        for (int nt = 0; nt < 4; nt++) {
            const int row0 = m0 + wM*64 + mt*16 + g;
            const int col  = n0 + wN*32 + nt*8 + tg*2;
            float2 bv = *(const float2*)(bias + col);
            float2 v0, v1;
            v0.x = acc[mt][nt][0] + bv.x;  v0.y = acc[mt][nt][1] + bv.y;
            v1.x = acc[mt][nt][2] + bv.x;  v1.y = acc[mt][nt][3] + bv.y;
            if (MODE == 0) {
                const int h = col >> 6, d = col & 63;
                {
                    const int b = row0 >> 11, s = row0 & 2047;
                    *(float2*)(C + ((size_t)((b*NH + h)*SEQ + s))*HD + d) = v0;
                }
                {
                    const int r1 = row0 + 8;
                    const int b = r1 >> 11, s = r1 & 2047;
                    *(float2*)(C + ((size_t)((b*NH + h)*SEQ + s))*HD + d) = v1;
                }
            } else {
                *(float2*)(C + (size_t)row0 * EMB + col) = v0;
                *(float2*)(C + (size_t)(row0 + 8) * EMB + col) = v1;
            }
        }
    }
}

// ===========================================================================
// Flash attention, packed-f32x2 math. One CTA per (b, h, 64-row q tile).
// 256 threads = 16x16, 4x4 micro-tiles, cols packed into f32x2 pairs.
// P stored transposed (PsT[j][r]) for vector PV reads.
// ===========================================================================
#define TPAD 68
#define ATTN_SMEM_BYTES ((4*64*TPAD + 32 + 128) * 4)

__global__ __launch_bounds__(256)
void attn_kernel(const int* __restrict__ responses, const int* __restrict__ mask,
                 const float* __restrict__ Wm, const float* __restrict__ bm)
{
    extern __shared__ float smem[];
    float* QsT = smem;                  // [64 d][TPAD] : Q[r][d]*invscale at [d][r]
    float* KsT = smem + 64*TPAD;        // [64 d][TPAD] : K[j][d] at [d][j]
    float* Vs  = smem + 2*64*TPAD;      // [64 j][TPAD] : V[j][c]
    float* PsT = smem + 3*64*TPAD;      // [64 j][TPAD] : P[r][j] at [j][r]
    float* tbl = smem + 4*64*TPAD;      // 25: qwk[a][c]*Wm[h]+bm[h]
    int*   rq  = (int*)(tbl + 32);      // 64
    int*   rk  = rq + 64;               // 64

    const int tid = threadIdx.x;
    const int tm  = tid >> 4;           // rows tm*4..+3
    const int tn  = tid & 15;           // cols tn*4..+3
    const int qb = blockIdx.x, h = blockIdx.y, b = blockIdx.z;
    const int q0 = qb * 64;
    const float invscale = 0.125f;

    if (tid < 25) {
        const int a = tid / 5, c = tid % 5;
        const float dq = (float)(a - c);
        tbl[tid] = (1.0f - dq*dq * (1.0f/16.0f)) * Wm[h] + bm[h];
    }
    if (tid < 64) rq[tid] = responses[b*SEQ + q0 + tid];

    const float* Qg = g_Q + ((size_t)(b*NH + h)*SEQ + q0)*HD;
    const float* Kg = g_K + ((size_t)(b*NH + h)*SEQ)*HD;
    const float* Vg = g_V + ((size_t)(b*NH + h)*SEQ)*HD;
    const int*   Mb = mask + (size_t)b*SEQ*SEQ;

    for (int e = tid; e < 1024; e += 256) {
        const int r = e >> 4, c4 = (e & 15) * 4;
        float4 v = *(const float4*)(Qg + r*HD + c4);
        QsT[(c4+0)*TPAD + r] = v.x * invscale;
        QsT[(c4+1)*TPAD + r] = v.y * invscale;
        QsT[(c4+2)*TPAD + r] = v.z * invscale;
        QsT[(c4+3)*TPAD + r] = v.w * invscale;
    }
    __syncthreads();

    int rqr[4];
    #pragma unroll
    for (int rr = 0; rr < 4; rr++) rqr[rr] = rq[tm*4 + rr];

    float m_i[4], l_i[4];
    unsigned long long Oacc2[4][2];
    #pragma unroll
    for (int rr = 0; rr < 4; rr++) {
        m_i[rr] = -1e30f; l_i[rr] = 0.f;
        Oacc2[rr][0] = 0ULL; Oacc2[rr][1] = 0ULL;
    }

    for (int kb = 0; kb < SEQ/64; kb++) {
        const int k0 = kb * 64;

        for (int e = tid; e < 1024; e += 256) {
            const int r = e >> 4, c4 = (e & 15) * 4;
            float4 kv = *(const float4*)(Kg + (k0 + r)*HD + c4);
            KsT[(c4+0)*TPAD + r] = kv.x;
            KsT[(c4+1)*TPAD + r] = kv.y;
            KsT[(c4+2)*TPAD + r] = kv.z;
            KsT[(c4+3)*TPAD + r] = kv.w;
            float4 vv = *(const float4*)(Vg + (k0 + r)*HD + c4);
            *(float4*)(Vs + r*TPAD + c4) = vv;
        }
        if (tid < 64) rk[tid] = responses[b*SEQ + k0 + tid];
        __syncthreads();

        // ---- scores via packed f32x2 ----
        unsigned long long sc2[4][2];
        #pragma unroll
        for (int rr = 0; rr < 4; rr++) { sc2[rr][0] = 0ULL; sc2[rr][1] = 0ULL; }

        #pragma unroll 16
        for (int d = 0; d < 64; d++) {
            float4 qa = *(const float4*)(QsT + d*TPAD + tm*4);
            float4 ka = *(const float4*)(KsT + d*TPAD + tn*4);
            const unsigned long long k01 = pk2(ka.x, ka.y);
            const unsigned long long k23 = pk2(ka.z, ka.w);
            const unsigned long long q0d = pk2(qa.x, qa.x);
            const unsigned long long q1d = pk2(qa.y, qa.y);
            const unsigned long long q2d = pk2(qa.z, qa.z);
            const unsigned long long q3d = pk2(qa.w, qa.w);
            fma2(sc2[0][0], q0d, k01); fma2(sc2[0][1], q0d, k23);
            fma2(sc2[1][0], q1d, k01); fma2(sc2[1][1], q1d, k23);
            fma2(sc2[2][0], q2d, k01); fma2(sc2[2][1], q2d, k23);
            fma2(sc2[3][0], q3d, k01); fma2(sc2[3][1], q3d, k23);
        }

        float sc[4][4];
        #pragma unroll
        for (int rr = 0; rr < 4; rr++) {
            upk2(sc[rr][0], sc[rr][1], sc2[rr][0]);
            upk2(sc[rr][2], sc[rr][3], sc2[rr][1]);
        }

        // ---- bias + mask ----
        int rkr[4];
        #pragma unroll
        for (int jj = 0; jj < 4; jj++) rkr[jj] = rk[tn*4 + jj];
        #pragma unroll
        for (int rr = 0; rr < 4; rr++) {
            const float* tr = tbl + rqr[rr]*5;
            int4 mv = *(const int4*)(Mb + (size_t)(q0 + tm*4 + rr)*SEQ + k0 + tn*4);
            sc[rr][0] = (mv.x == 0) ? -1e9f : sc[rr][0] + tr[rkr[0]];
            sc[rr][1] = (mv.y == 0) ? -1e9f : sc[rr][1] + tr[rkr[1]];
            sc[rr][2] = (mv.z == 0) ? -1e9f : sc[rr][2] + tr[rkr[2]];
            sc[rr][3] = (mv.w == 0) ? -1e9f : sc[rr][3] + tr[rkr[3]];
        }

        // ---- online softmax ----
        #pragma unroll
        for (int rr = 0; rr < 4; rr++) {
            float mx = fmaxf(fmaxf(sc[rr][0], sc[rr][1]), fmaxf(sc[rr][2], sc[rr][3]));
            mx = fmaxf(mx, __shfl_xor_sync(0xffffffffu, mx, 8));
            mx = fmaxf(mx, __shfl_xor_sync(0xffffffffu, mx, 4));
            mx = fmaxf(mx, __shfl_xor_sync(0xffffffffu, mx, 2));
            mx = fmaxf(mx, __shfl_xor_sync(0xffffffffu, mx, 1));
            const float mnew  = fmaxf(m_i[rr], mx);
            const float alpha = __expf(m_i[rr] - mnew);
            m_i[rr] = mnew;
            float rs = 0.f;
            #pragma unroll
            for (int jj = 0; jj < 4; jj++) {
                const float p = __expf(sc[rr][jj] - mnew);
                sc[rr][jj] = p;
                rs += p;
            }
            rs += __shfl_xor_sync(0xffffffffu, rs, 8);
            rs += __shfl_xor_sync(0xffffffffu, rs, 4);
            rs += __shfl_xor_sync(0xffffffffu, rs, 2);
            rs += __shfl_xor_sync(0xffffffffu, rs, 1);
            l_i[rr] = l_i[rr] * alpha + rs;
            const unsigned long long aa = pk2(alpha, alpha);
            mul2(Oacc2[rr][0], aa);
            mul2(Oacc2[rr][1], aa);
        }
        // store P transposed: PsT[j][r], vectorized over rows
        #pragma unroll
        for (int jj = 0; jj < 4; jj++) {
            float4 pv;
            pv.x = sc[0][jj]; pv.y = sc[1][jj]; pv.z = sc[2][jj]; pv.w = sc[3][jj];
            *(float4*)(PsT + (tn*4 + jj)*TPAD + tm*4) = pv;
        }
        __syncthreads();

        // ---- O += P @ V, packed over cols ----
        #pragma unroll 8
        for (int j = 0; j < 64; j++) {
            float4 vv = *(const float4*)(Vs + j*TPAD + tn*4);
            const unsigned long long v01 = pk2(vv.x, vv.y);
            const unsigned long long v23 = pk2(vv.z, vv.w);
            float4 pv = *(const float4*)(PsT + j*TPAD + tm*4);
            const unsigned long long p0d = pk2(pv.x, pv.x);
            const unsigned long long p1d = pk2(pv.y, pv.y);
            const unsigned long long p2d = pk2(pv.z, pv.z);
            const unsigned long long p3d = pk2(pv.w, pv.w);
            fma2(Oacc2[0][0], p0d, v01); fma2(Oacc2[0][1], p0d, v23);
            fma2(Oacc2[1][0], p1d, v01); fma2(Oacc2[1][1], p1d, v23);
            fma2(Oacc2[2][0], p2d, v01); fma2(Oacc2[2][1], p2d, v23);
            fma2(Oacc2[3][0], p3d, v01); fma2(Oacc2[3][1], p3d, v23);
        }
        __syncthreads();
    }

    // ---- epilogue ----
    float* Og = g_att + ((size_t)(b*NH + h)*SEQ + q0)*HD;
    #pragma unroll
    for (int rr = 0; rr < 4; rr++) {
        const float inv = 1.0f / l_i[rr];
        float o0, o1, o2, o3;
        upk2(o0, o1, Oacc2[rr][0]);
        upk2(o2, o3, Oacc2[rr][1]);
        float4 r;
        r.x = o0 * inv; r.y = o1 * inv; r.z = o2 * inv; r.w = o3 * inv;
        *(float4*)(Og + (tm*4 + rr)*HD + tn*4) = r;
    }
}

// ===========================================================================
extern "C" void kernel_launch(void* const* d_in, const int* in_sizes, int n_in,
                              void* d_out, int out_size)
{
    const float* query     = (const float*)d_in[0];
    const float* key_      = (const float*)d_in[1];
    const float* value     = (const float*)d_in[2];
    const int*   responses = (const int*)  d_in[3];
    const int*   mask      = (const int*)  d_in[4];
    const float* Wq = (const float*)d_in[5];
    const float* bq = (const float*)d_in[6];
    const float* Wk = (const float*)d_in[7];
    const float* bk = (const float*)d_in[8];
    const float* Wv = (const float*)d_in[9];
    const float* bv = (const float*)d_in[10];
    const float* Wo = (const float*)d_in[11];
    const float* bo = (const float*)d_in[12];
    const float* Wm = (const float*)d_in[13];
    const float* bmv = (const float*)d_in[14];
    float* out = (float*)d_out;

    float *qp, *kp, *vp, *ap;
    cudaGetSymbolAddress((void**)&qp, g_Q);
    cudaGetSymbolAddress((void**)&kp, g_K);
    cudaGetSymbolAddress((void**)&vp, g_V);
    cudaGetSymbolAddress((void**)&ap, g_att);

    cudaFuncSetAttribute(proj_mma<0>, cudaFuncAttributeMaxDynamicSharedMemorySize, PJ_SMEM);
    cudaFuncSetAttribute(proj_mma<1>, cudaFuncAttributeMaxDynamicSharedMemorySize, PJ_SMEM);
    cudaFuncSetAttribute(attn_kernel, cudaFuncAttributeMaxDynamicSharedMemorySize,
                         ATTN_SMEM_BYTES);

    dim3 pgrid(EMB/128, (BATCH*SEQ)/128);   // (8, 32)
    proj_mma<0><<<pgrid, 256, PJ_SMEM>>>(query, Wq, bq, qp);
    proj_mma<0><<<pgrid, 256, PJ_SMEM>>>(key_,  Wk, bk, kp);
    proj_mma<0><<<pgrid, 256, PJ_SMEM>>>(value, Wv, bv, vp);

    dim3 agrid(SEQ/64, NH, BATCH);          // (32, 16, 2)
    attn_kernel<<<agrid, 256, ATTN_SMEM_BYTES>>>(responses, mask, Wm, bmv);

    proj_mma<1><<<pgrid, 256, PJ_SMEM>>>(ap, Wo, bo, out);
}

// round 9
// speedup vs baseline: 2.3806x; 2.3806x over previous
#include <cuda_runtime.h>
#include <cuda_bf16.h>
#include <math.h>
#include <stdint.h>

#define BATCH 2
#define SEQ   2048
#define EMB   1024
#define NH    16
#define HD    64

// Scratch. g_V holds V TRANSPOSED: [B,H,D,S]. Others [B,H,S,D].
__device__ float g_Q[BATCH*NH*SEQ*HD];
__device__ float g_V[BATCH*NH*SEQ*HD];
__device__ float g_K[BATCH*NH*SEQ*HD];
__device__ float g_att[BATCH*NH*SEQ*HD];

// ===========================================================================
// helpers
// ===========================================================================
__device__ __forceinline__ uint32_t smem_u32(const void* p) {
    uint32_t a;
    asm("{ .reg .u64 t; cvta.to.shared.u64 t, %1; cvt.u32.u64 %0, t; }"
        : "=r"(a) : "l"(p));
    return a;
}
__device__ __forceinline__ uint32_t lds_u32(uint32_t a) {
    uint32_t v;
    asm volatile("ld.shared.b32 %0, [%1];" : "=r"(v) : "r"(a));
    return v;
}
__device__ __forceinline__ void sts_v2(uint32_t a, uint32_t x, uint32_t y) {
    asm volatile("st.shared.v2.b32 [%0], {%1, %2};" :: "r"(a), "r"(x), "r"(y) : "memory");
}

// bf16 MMA m16n8k16, fp32 accumulate (portable path, sm_80+) — layout
// validated by the passing R8 projection kernel.
__device__ __forceinline__ void mma16816(float* c, const uint32_t* a, const uint32_t* b) {
    asm volatile(
        "mma.sync.aligned.m16n8k16.row.col.f32.bf16.bf16.f32 "
        "{%0,%1,%2,%3}, {%4,%5,%6,%7}, {%8,%9}, {%0,%1,%2,%3};"
        : "+f"(c[0]), "+f"(c[1]), "+f"(c[2]), "+f"(c[3])
        : "r"(a[0]), "r"(a[1]), "r"(a[2]), "r"(a[3]), "r"(b[0]), "r"(b[1]));
}

__device__ __forceinline__ uint32_t pkbf(__nv_bfloat16 a, __nv_bfloat16 b) {
    return ((uint32_t)__bfloat16_as_ushort(b) << 16) | __bfloat16_as_ushort(a);
}

// split float pair -> bf16x2 hi plane + lo plane
__device__ __forceinline__ void split2(float x, float y, uint32_t& hi, uint32_t& lo) {
    __nv_bfloat16 hx = __float2bfloat16(x);
    __nv_bfloat16 hy = __float2bfloat16(y);
    hi = pkbf(hx, hy);
    lo = pkbf(__float2bfloat16(x - __bfloat162float(hx)),
              __float2bfloat16(y - __bfloat162float(hy)));
}

// split float4 into bf16 hi plane (x,y) and lo plane (z,w)
__device__ __forceinline__ uint4 split4(float4 v) {
    uint4 u;
    split2(v.x, v.y, u.x, u.z);
    split2(v.z, v.w, u.y, u.w);
    return u;
}

// ===========================================================================
// MMA projection GEMM: C[4096][1024] = A(4096x1024) * W(1024x1024)^T + bias
// fp32 via bf16 3-plane split. CTA tile 128x128, 8 warps (2Mx4N), warp tile
// 64x32, BK=32, double-buffered smem.
// MODE 0: A linear, C -> [B,H,S,D].  MODE 1: A from [B,H,S,D], C linear.
// MODE 2: A linear, C -> [B,H,D,S]  (transposed V for attention B-frags).
// ===========================================================================
#define BK      32
#define PITCHB  80                  // bytes per smem row (40 bf16)
#define PLANE   (128*PITCHB)        // 10240 B
#define BUFSZ   (4*PLANE)           // Ahi,Alo,Whi,Wlo = 40960 B
#define PJ_SMEM (2*BUFSZ)           // 81920 B

template<int MODE>
__global__ void __launch_bounds__(256, 1)
proj_mma(const float* __restrict__ A, const float* __restrict__ W,
         const float* __restrict__ bias, float* __restrict__ C)
{
    extern __shared__ char smp[];
    const uint32_t sb = smem_u32(smp);
    const int tid  = threadIdx.x;
    const int wid  = tid >> 5, lane = tid & 31;
    const int g    = lane >> 2, tg = lane & 3;
    const int wM   = wid >> 2;          // 0..1
    const int wN   = wid & 3;           // 0..3
    const int n0   = blockIdx.x * 128;
    const int m0   = blockIdx.y * 128;

    float acc[4][4][4];
    #pragma unroll
    for (int mt = 0; mt < 4; mt++)
        #pragma unroll
        for (int nt = 0; nt < 4; nt++)
            #pragma unroll
            for (int i = 0; i < 4; i++) acc[mt][nt][i] = 0.f;

    float4 avA[4], avW[4];

    auto gload = [&](int kb) {
        const int k0 = kb * BK;
        #pragma unroll
        for (int i = 0; i < 4; i++) {
            const int idx = i * 256 + tid;
            const int r = idx >> 3, c4 = (idx & 7) << 2;
            if (MODE == 1) {
                const int m = m0 + r;
                const int b = m >> 11, s = m & 2047;
                const int k = k0 + c4;
                const int h = k >> 6, d = k & 63;
                avA[i] = *(const float4*)(A + ((size_t)((b*NH + h)*SEQ + s))*HD + d);
            } else {
                avA[i] = *(const float4*)(A + (size_t)(m0 + r) * EMB + k0 + c4);
            }
            avW[i] = *(const float4*)(W + (size_t)(n0 + r) * EMB + k0 + c4);
        }
    };

    auto cvtstore = [&](int buf) {
        const uint32_t base = sb + (uint32_t)buf * BUFSZ;
        #pragma unroll
        for (int i = 0; i < 4; i++) {
            const int idx = i * 256 + tid;
            const int r = idx >> 3, c4 = (idx & 7) << 2;
            const uint32_t off = (uint32_t)(r * PITCHB + c4 * 2);
            uint4 ua = split4(avA[i]);
            sts_v2(base + off,              ua.x, ua.y);
            sts_v2(base + PLANE + off,      ua.z, ua.w);
            uint4 uw = split4(avW[i]);
            sts_v2(base + 2*PLANE + off,    uw.x, uw.y);
            sts_v2(base + 3*PLANE + off,    uw.z, uw.w);
        }
    };

    auto mma_chunk = [&](int buf) {
        const uint32_t aH = sb + (uint32_t)buf * BUFSZ;
        const uint32_t aL = aH + PLANE;
        const uint32_t bH = aH + 2*PLANE;
        const uint32_t bL = aH + 3*PLANE;
        #pragma unroll
        for (int ks = 0; ks < 2; ks++) {
            const uint32_t kOff = (uint32_t)(ks * 32);
            uint32_t Ah[4][4], Al[4][4], Bh[4][2], Bl[4][2];
            #pragma unroll
            for (int mt = 0; mt < 4; mt++) {
                const uint32_t ro = (uint32_t)((wM*64 + mt*16 + g) * PITCHB) + kOff + tg*4;
                Ah[mt][0] = lds_u32(aH + ro);
                Ah[mt][1] = lds_u32(aH + ro + 8*PITCHB);
                Ah[mt][2] = lds_u32(aH + ro + 16);
                Ah[mt][3] = lds_u32(aH + ro + 8*PITCHB + 16);
                Al[mt][0] = lds_u32(aL + ro);
                Al[mt][1] = lds_u32(aL + ro + 8*PITCHB);
                Al[mt][2] = lds_u32(aL + ro + 16);
                Al[mt][3] = lds_u32(aL + ro + 8*PITCHB + 16);
            }
            #pragma unroll
            for (int nt = 0; nt < 4; nt++) {
                const uint32_t ro = (uint32_t)((wN*32 + nt*8 + g) * PITCHB) + kOff + tg*4;
                Bh[nt][0] = lds_u32(bH + ro);
                Bh[nt][1] = lds_u32(bH + ro + 16);
                Bl[nt][0] = lds_u32(bL + ro);
                Bl[nt][1] = lds_u32(bL + ro + 16);
            }
            #pragma unroll
            for (int mt = 0; mt < 4; mt++)
                #pragma unroll
                for (int nt = 0; nt < 4; nt++)
                    mma16816(acc[mt][nt], Ah[mt], Bh[nt]);
            #pragma unroll
            for (int mt = 0; mt < 4; mt++)
                #pragma unroll
                for (int nt = 0; nt < 4; nt++)
                    mma16816(acc[mt][nt], Al[mt], Bh[nt]);
            #pragma unroll
            for (int mt = 0; mt < 4; mt++)
                #pragma unroll
                for (int nt = 0; nt < 4; nt++)
                    mma16816(acc[mt][nt], Ah[mt], Bl[nt]);
        }
    };

    gload(0);
    cvtstore(0);
    __syncthreads();

    for (int kb = 0; kb < EMB/BK; kb++) {
        const int cur = kb & 1;
        if (kb < EMB/BK - 1) gload(kb + 1);
        mma_chunk(cur);
        if (kb < EMB/BK - 1) {
            cvtstore(cur ^ 1);
            __syncthreads();
        }
    }

    #pragma unroll
    for (int mt = 0; mt < 4; mt++) {
        #pragma unroll
        for (int nt = 0; nt < 4; nt++) {
            const int row0 = m0 + wM*64 + mt*16 + g;
            const int col  = n0 + wN*32 + nt*8 + tg*2;
            float2 bv = *(const float2*)(bias + col);
            float2 v0, v1;
            v0.x = acc[mt][nt][0] + bv.x;  v0.y = acc[mt][nt][1] + bv.y;
            v1.x = acc[mt][nt][2] + bv.x;  v1.y = acc[mt][nt][3] + bv.y;
            if (MODE == 0) {
                const int h = col >> 6, d = col & 63;
                {
                    const int b = row0 >> 11, s = row0 & 2047;
                    *(float2*)(C + ((size_t)((b*NH + h)*SEQ + s))*HD + d) = v0;
                }
                {
                    const int r1 = row0 + 8;
                    const int b = r1 >> 11, s = r1 & 2047;
                    *(float2*)(C + ((size_t)((b*NH + h)*SEQ + s))*HD + d) = v1;
                }
            } else if (MODE == 2) {
                const int h = col >> 6, d = col & 63;
                const int b = row0 >> 11, s = row0 & 2047;
                float* base = C + ((size_t)(b*NH + h))*HD*SEQ;
                base[(size_t)(d  )*SEQ + s    ] = v0.x;
                base[(size_t)(d+1)*SEQ + s    ] = v0.y;
                base[(size_t)(d  )*SEQ + s + 8] = v1.x;
                base[(size_t)(d+1)*SEQ + s + 8] = v1.y;
            } else {
                *(float2*)(C + (size_t)row0 * EMB + col) = v0;
                *(float2*)(C + (size_t)(row0 + 8) * EMB + col) = v1;
            }
        }
    }
}

// ===========================================================================
// Flash attention via warp-level bf16 MMA (FA2-style).
// CTA: 256 threads = 8 warps, each warp owns 16 q-rows (CTA = 128 rows).
// K-tiles of 64. Q A-frags preloaded (3-plane split). K/VsT staged in smem
// as bf16 hi/lo, pitch 144B (conflict-free reads). S c-frags reused directly
// as PV A-frags (FA2 register identity). V read from g_V transposed [B,H,D,S].
// ===========================================================================
#define AT_PITCH 144
#define AT_KHI   0
#define AT_KLO   (64*AT_PITCH)          //  9216
#define AT_VHI   (2*64*AT_PITCH)        // 18432
#define AT_VLO   (3*64*AT_PITCH)        // 27648
#define AT_RKF   (4*64*AT_PITCH)        // 36864
#define AT_SMEM  (AT_RKF + 256 + 64)

__global__ void __launch_bounds__(256)
attn_mma(const int* __restrict__ responses, const int* __restrict__ mask,
         const float* __restrict__ Wm, const float* __restrict__ bm)
{
    extern __shared__ char sma[];
    const uint32_t sb = smem_u32(sma);
    float* rkf = (float*)(sma + AT_RKF);

    const int tid  = threadIdx.x;
    const int wid  = tid >> 5, lane = tid & 31;
    const int g    = lane >> 2, tg = lane & 3;
    const int qb = blockIdx.x, h = blockIdx.y, b = blockIdx.z;
    const int q0 = qb * 128;
    const int rowA = q0 + wid * 16 + g;        // global q row of c0,c1
    const int rowB = rowA + 8;                 // global q row of c2,c3

    const float Wmh = Wm[h], bmh = bm[h];
    const float A0c = Wmh + bmh;
    const float A1c = Wmh * 0.0625f;
    const float rqA = (float)responses[b*SEQ + rowA];
    const float rqB = (float)responses[b*SEQ + rowB];

    const float* Qg  = g_Q + ((size_t)(b*NH + h)*SEQ)*HD;
    const float* Kg  = g_K + ((size_t)(b*NH + h)*SEQ)*HD;
    const float* VTg = g_V + ((size_t)(b*NH + h))*HD*SEQ;   // [d][s]
    const int*   Mb  = mask + (size_t)b*SEQ*SEQ;
    const int*   rkp = responses + b*SEQ;

    // ---- preload Q A-frags, scaled by 1/8, 3-plane split ----
    uint32_t Qhi[4][4], Qlo[4][4];
    #pragma unroll
    for (int kc = 0; kc < 4; kc++) {
        const int c0 = kc*16 + tg*2;
        float2 f0 = *(const float2*)(Qg + (size_t)rowA*HD + c0);
        float2 f1 = *(const float2*)(Qg + (size_t)rowB*HD + c0);
        float2 f2 = *(const float2*)(Qg + (size_t)rowA*HD + c0 + 8);
        float2 f3 = *(const float2*)(Qg + (size_t)rowB*HD + c0 + 8);
        split2(f0.x*0.125f, f0.y*0.125f, Qhi[kc][0], Qlo[kc][0]);
        split2(f1.x*0.125f, f1.y*0.125f, Qhi[kc][1], Qlo[kc][1]);
        split2(f2.x*0.125f, f2.y*0.125f, Qhi[kc][2], Qlo[kc][2]);
        split2(f3.x*0.125f, f3.y*0.125f, Qhi[kc][3], Qlo[kc][3]);
    }

    float o[8][4];
    #pragma unroll
    for (int dt = 0; dt < 8; dt++)
        #pragma unroll
        for (int i = 0; i < 4; i++) o[dt][i] = 0.f;
    float mA = -1e30f, mB = -1e30f, lA = 0.f, lB = 0.f;

    for (int kt = 0; kt < SEQ/64; kt++) {
        const int k0 = kt * 64;

        // ---- stage K (rows j, cols d) and VsT (rows d, cols j) as bf16 hi/lo ----
        #pragma unroll
        for (int e = tid; e < 1024; e += 256) {
            const int r = e >> 4, c4 = (e & 15) * 4;
            float4 kv = *(const float4*)(Kg + (size_t)(k0 + r)*HD + c4);
            uint4 uk = split4(kv);
            const uint32_t ko = (uint32_t)(r * AT_PITCH + c4 * 2);
            sts_v2(sb + AT_KHI + ko, uk.x, uk.y);
            sts_v2(sb + AT_KLO + ko, uk.z, uk.w);
            float4 vv = *(const float4*)(VTg + (size_t)r*SEQ + k0 + c4);
            uint4 uv = split4(vv);
            sts_v2(sb + AT_VHI + ko, uv.x, uv.y);
            sts_v2(sb + AT_VLO + ko, uv.z, uv.w);
        }
        if (tid < 64) rkf[tid] = (float)rkp[k0 + tid];
        __syncthreads();

        // ---- QK: S[16][64] via m16n8k16, 3 planes ----
        float c[8][4];
        #pragma unroll
        for (int nt = 0; nt < 8; nt++)
            #pragma unroll
            for (int i = 0; i < 4; i++) c[nt][i] = 0.f;

        #pragma unroll
        for (int kc = 0; kc < 4; kc++) {
            #pragma unroll
            for (int nt = 0; nt < 8; nt++) {
                const uint32_t ro = (uint32_t)((nt*8 + g) * AT_PITCH + kc*32 + tg*4);
                uint32_t Bh[2], Bl[2];
                Bh[0] = lds_u32(sb + AT_KHI + ro);
                Bh[1] = lds_u32(sb + AT_KHI + ro + 16);
                Bl[0] = lds_u32(sb + AT_KLO + ro);
                Bl[1] = lds_u32(sb + AT_KLO + ro + 16);
                mma16816(c[nt], Qhi[kc], Bh);
                mma16816(c[nt], Qlo[kc], Bh);
                mma16816(c[nt], Qhi[kc], Bl);
            }
        }

        // ---- bias (arithmetic QWK) + mask ----
        #pragma unroll
        for (int nt = 0; nt < 8; nt++) {
            const int col = k0 + nt*8 + tg*2;
            float2 rk2 = *(const float2*)(rkf + nt*8 + tg*2);
            int2 mvA = *(const int2*)(Mb + (size_t)rowA*SEQ + col);
            int2 mvB = *(const int2*)(Mb + (size_t)rowB*SEQ + col);
            float d0 = rqA - rk2.x, d1 = rqA - rk2.y;
            float d2 = rqB - rk2.x, d3 = rqB - rk2.y;
            c[nt][0] = (mvA.x == 0) ? -1e9f : c[nt][0] + A0c - A1c*d0*d0;
            c[nt][1] = (mvA.y == 0) ? -1e9f : c[nt][1] + A0c - A1c*d1*d1;
            c[nt][2] = (mvB.x == 0) ? -1e9f : c[nt][2] + A0c - A1c*d2*d2;
            c[nt][3] = (mvB.y == 0) ? -1e9f : c[nt][3] + A0c - A1c*d3*d3;
        }

        // ---- online softmax (rows A and B; quad shfl over tg) ----
        float mxA = -1e30f, mxB = -1e30f;
        #pragma unroll
        for (int nt = 0; nt < 8; nt++) {
            mxA = fmaxf(mxA, fmaxf(c[nt][0], c[nt][1]));
            mxB = fmaxf(mxB, fmaxf(c[nt][2], c[nt][3]));
        }
        mxA = fmaxf(mxA, __shfl_xor_sync(0xffffffffu, mxA, 1));
        mxA = fmaxf(mxA, __shfl_xor_sync(0xffffffffu, mxA, 2));
        mxB = fmaxf(mxB, __shfl_xor_sync(0xffffffffu, mxB, 1));
        mxB = fmaxf(mxB, __shfl_xor_sync(0xffffffffu, mxB, 2));

        const float mnA = fmaxf(mA, mxA), mnB = fmaxf(mB, mxB);
        const float alA = __expf(mA - mnA), alB = __expf(mB - mnB);
        mA = mnA; mB = mnB;

        float rsA = 0.f, rsB = 0.f;
        #pragma unroll
        for (int nt = 0; nt < 8; nt++) {
            c[nt][0] = __expf(c[nt][0] - mnA);  rsA += c[nt][0];
            c[nt][1] = __expf(c[nt][1] - mnA);  rsA += c[nt][1];
            c[nt][2] = __expf(c[nt][2] - mnB);  rsB += c[nt][2];
            c[nt][3] = __expf(c[nt][3] - mnB);  rsB += c[nt][3];
        }
        rsA += __shfl_xor_sync(0xffffffffu, rsA, 1);
        rsA += __shfl_xor_sync(0xffffffffu, rsA, 2);
        rsB += __shfl_xor_sync(0xffffffffu, rsB, 1);
        rsB += __shfl_xor_sync(0xffffffffu, rsB, 2);
        lA = lA * alA + rsA;
        lB = lB * alB + rsB;

        #pragma unroll
        for (int dt = 0; dt < 8; dt++) {
            o[dt][0] *= alA; o[dt][1] *= alA;
            o[dt][2] *= alB; o[dt][3] *= alB;
        }

        // ---- P c-frags -> PV A-frags (FA2 identity), bf16 hi/lo ----
        uint32_t Phi[4][4], Plo[4][4];
        #pragma unroll
        for (int kc = 0; kc < 4; kc++) {
            split2(c[2*kc  ][0], c[2*kc  ][1], Phi[kc][0], Plo[kc][0]);
            split2(c[2*kc  ][2], c[2*kc  ][3], Phi[kc][1], Plo[kc][1]);
            split2(c[2*kc+1][0], c[2*kc+1][1], Phi[kc][2], Plo[kc][2]);
            split2(c[2*kc+1][2], c[2*kc+1][3], Phi[kc][3], Plo[kc][3]);
        }

        // ---- PV: O[16][64] += P[16][64] * V[64][64], 3 planes ----
        #pragma unroll
        for (int kc = 0; kc < 4; kc++) {
            #pragma unroll
            for (int dt = 0; dt < 8; dt++) {
                const uint32_t ro = (uint32_t)((dt*8 + g) * AT_PITCH + kc*32 + tg*4);
                uint32_t Vh[2], Vl[2];
                Vh[0] = lds_u32(sb + AT_VHI + ro);
                Vh[1] = lds_u32(sb + AT_VHI + ro + 16);
                Vl[0] = lds_u32(sb + AT_VLO + ro);
                Vl[1] = lds_u32(sb + AT_VLO + ro + 16);
                mma16816(o[dt], Phi[kc], Vh);
                mma16816(o[dt], Plo[kc], Vh);
                mma16816(o[dt], Phi[kc], Vl);
            }
        }
        __syncthreads();
    }

    // ---- epilogue: normalize, store [B,H,S,D] ----
    const float invA = 1.0f / lA, invB = 1.0f / lB;
    float* Og = g_att + ((size_t)(b*NH + h)*SEQ)*HD;
    #pragma unroll
    for (int dt = 0; dt < 8; dt++) {
        const int col = dt*8 + tg*2;
        float2 vA, vB;
        vA.x = o[dt][0] * invA;  vA.y = o[dt][1] * invA;
        vB.x = o[dt][2] * invB;  vB.y = o[dt][3] * invB;
        *(float2*)(Og + (size_t)rowA*HD + col) = vA;
        *(float2*)(Og + (size_t)rowB*HD + col) = vB;
    }
}

// ===========================================================================
extern "C" void kernel_launch(void* const* d_in, const int* in_sizes, int n_in,
                              void* d_out, int out_size)
{
    const float* query     = (const float*)d_in[0];
    const float* key_      = (const float*)d_in[1];
    const float* value     = (const float*)d_in[2];
    const int*   responses = (const int*)  d_in[3];
    const int*   mask      = (const int*)  d_in[4];
    const float* Wq = (const float*)d_in[5];
    const float* bq = (const float*)d_in[6];
    const float* Wk = (const float*)d_in[7];
    const float* bk = (const float*)d_in[8];
    const float* Wv = (const float*)d_in[9];
    const float* bv = (const float*)d_in[10];
    const float* Wo = (const float*)d_in[11];
    const float* bo = (const float*)d_in[12];
    const float* Wm = (const float*)d_in[13];
    const float* bmv = (const float*)d_in[14];
    float* out = (float*)d_out;

    float *qp, *kp, *vp, *ap;
    cudaGetSymbolAddress((void**)&qp, g_Q);
    cudaGetSymbolAddress((void**)&kp, g_K);
    cudaGetSymbolAddress((void**)&vp, g_V);
    cudaGetSymbolAddress((void**)&ap, g_att);

    cudaFuncSetAttribute(proj_mma<0>, cudaFuncAttributeMaxDynamicSharedMemorySize, PJ_SMEM);
    cudaFuncSetAttribute(proj_mma<1>, cudaFuncAttributeMaxDynamicSharedMemorySize, PJ_SMEM);
    cudaFuncSetAttribute(proj_mma<2>, cudaFuncAttributeMaxDynamicSharedMemorySize, PJ_SMEM);
    cudaFuncSetAttribute(attn_mma,    cudaFuncAttributeMaxDynamicSharedMemorySize, AT_SMEM);

    dim3 pgrid(EMB/128, (BATCH*SEQ)/128);   // (8, 32)
    proj_mma<0><<<pgrid, 256, PJ_SMEM>>>(query, Wq, bq, qp);
    proj_mma<0><<<pgrid, 256, PJ_SMEM>>>(key_,  Wk, bk, kp);
    proj_mma<2><<<pgrid, 256, PJ_SMEM>>>(value, Wv, bv, vp);   // V transposed

    dim3 agrid(SEQ/128, NH, BATCH);          // (16, 16, 2)
    attn_mma<<<agrid, 256, AT_SMEM>>>(responses, mask, Wm, bmv);

    proj_mma<1><<<pgrid, 256, PJ_SMEM>>>(ap, Wo, bo, out);
}